// round 1
// baseline (speedup 1.0000x reference)
#include <cuda_runtime.h>

// x: [8, 256, 16, 56, 56] fp32, weight: [256, 1, 3] fp32
// y[n,c,t,h,w] = w[c,0]*x[t-2] + w[c,1]*x[t] + w[c,2]*x[t+2]  (zero outside t range)
//
// Layout facts:
//   HW  = 56*56 = 3136 contiguous floats per (n,c,t)
//   T   = 16, stride between t-planes = 3136 floats
//   NC  = 8*256 = 2048 lines
// One thread handles one (n, c, hw4-chunk) and the full t-line:
// 16 float4 loads (each input read exactly once), 16 float4 stores.

__global__ __launch_bounds__(256) void tshift_kernel(
    const float* __restrict__ x,
    const float* __restrict__ w,
    float* __restrict__ y)
{
    constexpr int HW4 = 3136 / 4;      // 784 float4 per t-plane
    constexpr int T = 16;
    constexpr int THW = T * 3136;      // floats per (n,c) line

    int idx = blockIdx.x * blockDim.x + threadIdx.x;   // 0 .. 2048*784-1 exactly
    int nc = idx / HW4;
    int q  = idx - nc * HW4;
    int c  = nc & 255;

    float w0 = __ldg(&w[c * 3 + 0]);
    float w1 = __ldg(&w[c * 3 + 1]);
    float w2 = __ldg(&w[c * 3 + 2]);

    const float4* xp = reinterpret_cast<const float4*>(x + (long)nc * THW) + q;
    float4*       yp = reinterpret_cast<float4*>      (y + (long)nc * THW) + q;

    // Front-batched loads: each input element read exactly once, MLP=16.
    float4 xv[T];
#pragma unroll
    for (int t = 0; t < T; t++)
        xv[t] = xp[(long)t * HW4];

#pragma unroll
    for (int t = 0; t < T; t++) {
        float4 r;
        r.x = w1 * xv[t].x;
        r.y = w1 * xv[t].y;
        r.z = w1 * xv[t].z;
        r.w = w1 * xv[t].w;
        if (t >= 2) {
            r.x = fmaf(w0, xv[t - 2].x, r.x);
            r.y = fmaf(w0, xv[t - 2].y, r.y);
            r.z = fmaf(w0, xv[t - 2].z, r.z);
            r.w = fmaf(w0, xv[t - 2].w, r.w);
        }
        if (t < T - 2) {
            r.x = fmaf(w2, xv[t + 2].x, r.x);
            r.y = fmaf(w2, xv[t + 2].y, r.y);
            r.z = fmaf(w2, xv[t + 2].z, r.z);
            r.w = fmaf(w2, xv[t + 2].w, r.w);
        }
        yp[(long)t * HW4] = r;
    }
}

extern "C" void kernel_launch(void* const* d_in, const int* in_sizes, int n_in,
                              void* d_out, int out_size)
{
    const float* x = (const float*)d_in[0];
    const float* w = (const float*)d_in[1];
    float* y = (float*)d_out;

    // total threads = 2048 * 784 = 1,605,632 -> 6272 blocks of 256 (exact)
    constexpr int total = 2048 * 784;
    constexpr int threads = 256;
    constexpr int blocks = total / threads;
    tshift_kernel<<<blocks, threads>>>(x, w, y);
}